// round 13
// baseline (speedup 1.0000x reference)
#include <cuda_runtime.h>
#include <cuda_fp16.h>
#include <stdint.h>
#include <math.h>

#define N_NODES 10000
#define N_EDGES 160000
#define BATCH 4
#define T_STEPS 16
#define HID 64
#define M_ROWS 40000
#define M_PAD  40064             // 626 * 64
#define KDIM 208                 // 13 * 16
#define NKS 13
#define SPITCH 216               // smem A pitch in halves (432B: conflict-free ldmatrix)

typedef uint32_t u32;

// U channel layout (K axis, permuted for aligned agg stores):
//   [0..63] = h|rh   [64..127] = aggF(h|rh)   [128..191] = aggB(h|rh)
//   [192]=x [193]=aggF_x [194]=aggB_x [195..207]=0
// Permutation folded into the B fragment tables at build time.

// ---------------- device scratch ----------------
__device__ float g_h [M_PAD*HID];
__device__ float g_z [M_PAD*HID];
__device__ __align__(16) __half g_hb [M_PAD*HID];   // fp16 mirror of h
__device__ __align__(16) __half g_rhb[M_PAD*HID];   // fp16 rh (only representation)
__device__ __align__(16) __half g_U  [(size_t)M_PAD*KDIM];   // fp16 activations (GEMM A)
__device__ __align__(8)  __half g_xc [(size_t)T_STEPS*M_PAD*4]; // {x, aggFx, aggBx, 0} per (t,row)
__device__ float g_deg_out[N_NODES], g_deg_in[N_NODES];
__device__ int   g_cntF[N_NODES], g_cntB[N_NODES];
__device__ int   g_offF[N_NODES+1], g_offB[N_NODES+1];
__device__ int   g_srcF[N_EDGES], g_srcB[N_EDGES];
__device__ float g_wF[N_EDGES],  g_wB[N_EDGES];
// Prepacked B fragment tables (fp16 hi/lo): [ks][split][natom][lane] -> uint2
__device__ uint2 g_BfZr[NKS*2*16*32];
__device__ uint2 g_BfC [NKS*2*8*32];
__device__ float g_bzr[128], g_bh[64];

__device__ __forceinline__ u32 smem_u32(const void* p) {
    u32 a;
    asm("{ .reg .u64 t; cvta.to.shared.u64 t, %1; cvt.u32.u64 %0, t; }" : "=r"(a) : "l"(p));
    return a;
}

// ---------------- prep 1: single-block histogram + degree + scan ----------------
__global__ void prep_scan(const int* __restrict__ ei, const float* __restrict__ ew) {
    extern __shared__ int sm[];
    int*   cF = sm;
    int*   cB = sm + 10240;
    float* dF = (float*)(sm + 20480);
    float* dB = (float*)(sm + 30720);
    __shared__ int sb[1024];
    int t = threadIdx.x;

    for (int i = t; i < 10240; i += 1024) { cF[i]=0; cB[i]=0; dF[i]=0.f; dB[i]=0.f; }
    __syncthreads();

    for (int e = t; e < N_EDGES; e += 1024) {
        int r = ei[e], c = ei[N_EDGES + e];
        float w = ew[e];
        atomicAdd(&cF[r], 1);
        atomicAdd(&cB[c], 1);
        atomicAdd(&dF[r], w);
        atomicAdd(&dB[c], w);
    }
    __syncthreads();

    for (int i = t; i < N_NODES; i += 1024) {
        g_deg_out[i] = dF[i];
        g_deg_in [i] = dB[i];
        g_cntF[i] = 0;
        g_cntB[i] = 0;
    }

    for (int pass = 0; pass < 2; pass++) {
        const int* cnt = pass == 0 ? cF : cB;
        int*       off = pass == 0 ? g_offF : g_offB;
        int carry = 0;
        for (int base = 0; base < N_NODES; base += 1024) {
            int v = (base + t < N_NODES) ? cnt[base + t] : 0;
            sb[t] = v; __syncthreads();
            for (int o = 1; o < 1024; o <<= 1) {
                int y = (t >= o) ? sb[t - o] : 0;
                __syncthreads();
                sb[t] += y;
                __syncthreads();
            }
            if (base + t < N_NODES) off[base + t] = carry + sb[t] - v;
            carry += sb[1023];
            __syncthreads();
        }
        if (t == 0) off[N_NODES] = carry;
        __syncthreads();
    }
}

// ---------------- prep 2: edge fill + zero h + B fragment build ----------------
#define FILL_BLKS 625
#define ZEROH_BLKS 10016          // M_PAD*HID/256
#define ZRE (NKS*2*16*32)         // 13312
#define CE  (NKS*2*8*32)          // 6656
#define BFRAG_BLKS 78

// wval over the ORIGINAL channel indexing
__device__ __forceinline__ float wval(const float* W, int c, int j) {
    if (c >= 195) return 0.f;
    if (c < 65)  return W[(0*65 + c)*64 + j] + W[(2*65 + c)*64 + j];
    if (c < 130) return W[(1*65 + (c-65))*64 + j];
    return W[(3*65 + (c-130))*64 + j];
}
// map NEW (permuted) channel -> ORIGINAL channel
__device__ __forceinline__ int newc(int c) {
    if (c < 64)  return c + 1;
    if (c < 128) return c + 2;
    if (c < 192) return c + 3;
    if (c == 192) return 0;
    if (c == 193) return 65;
    if (c == 194) return 130;
    return 999;
}
__device__ __forceinline__ u32 packh(float a, float b) {
    __half2 t = __floats2half2_rn(a, b);
    return *(u32*)&t;
}
__global__ void fill_misc(const int* __restrict__ ei, const float* __restrict__ ew,
                          const float* __restrict__ Wz, const float* __restrict__ bz,
                          const float* __restrict__ Wr, const float* __restrict__ br,
                          const float* __restrict__ Wh, const float* __restrict__ bh) {
    int blk = blockIdx.x, tid = threadIdx.x;
    if (blk < FILL_BLKS) {
        int e = blk*256 + tid;
        if (e >= N_EDGES) return;
        int r = ei[e], c = ei[N_EDGES + e];
        float w = ew[e];
        float dof = g_deg_out[r];
        float cf = (dof > 0.f) ? w / dof : 0.f;
        int p = g_offF[r] + atomicAdd(&g_cntF[r], 1);
        g_srcF[p] = c; g_wF[p] = cf;
        float din = g_deg_in[c];
        float cb = (din > 0.f) ? w / din : 0.f;
        int q = g_offB[c] + atomicAdd(&g_cntB[c], 1);
        g_srcB[q] = r; g_wB[q] = cb;
    } else if (blk < FILL_BLKS + ZEROH_BLKS) {
        int i = (blk - FILL_BLKS)*256 + tid;
        if (i < M_PAD*HID) { g_h[i] = 0.f; g_hb[i] = __float2half(0.f); }
    } else {
        int idx = (blk - FILL_BLKS - ZEROH_BLKS)*256 + tid;
        if (idx < 128) g_bzr[idx] = (idx < 64) ? bz[idx] : br[idx - 64];
        if (idx < 64)  g_bh[idx] = bh[idx];
        if (idx < ZRE + CE) {
            int natot = (idx < ZRE) ? 16 : 8;
            int e = (idx < ZRE) ? idx : idx - ZRE;
            int lane = e & 31;
            int na   = (e >> 5) % natot;
            int split = (e / (32*natot)) & 1;
            int ks    = e / (64*natot);
            int k0 = ks*16 + (lane & 3)*2;
            int n  = na*8 + (lane >> 2);
            float v[4];
            if (idx < ZRE) {
                const float* W = (n < 64) ? Wz : Wr;
                int j = n & 63;
                v[0] = wval(W, newc(k0),   j); v[1] = wval(W, newc(k0+1), j);
                v[2] = wval(W, newc(k0+8), j); v[3] = wval(W, newc(k0+9), j);
            } else {
                v[0] = wval(Wh, newc(k0),   n); v[1] = wval(Wh, newc(k0+1), n);
                v[2] = wval(Wh, newc(k0+8), n); v[3] = wval(Wh, newc(k0+9), n);
            }
            float p[4];
            for (int i2 = 0; i2 < 4; i2++) {
                float hi = __half2float(__float2half(v[i2]));
                p[i2] = split ? (v[i2] - hi) : hi;
            }
            uint2 frag = make_uint2(packh(p[0], p[1]), packh(p[2], p[3]));
            if (idx < ZRE) g_BfZr[e] = frag; else g_BfC[e] = frag;
        }
    }
}

// ---------------- prep 3: x-channel aggregation for ALL steps (h-independent) ----
__global__ void xagg_kernel(const float* __restrict__ x_dis) {
    int idx = blockIdx.x*blockDim.x + threadIdx.x;     // over 16 * 40000
    if (idx >= T_STEPS*M_ROWS) return;
    int t = idx / M_ROWS, r = idx % M_ROWS;
    int n = r >> 2, b = r & 3;
    const float* __restrict__ xb = x_dis + (size_t)(b*T_STEPS + t)*N_NODES;
    float xv = xb[n];
    float ax[2];
    for (int dir = 0; dir < 2; dir++) {
        const int*   off = dir == 0 ? g_offF : g_offB;
        const int*   src = dir == 0 ? g_srcF : g_srcB;
        const float* ww  = dir == 0 ? g_wF   : g_wB;
        float a = 0.f;
        int e1 = off[n + 1];
        for (int e = off[n]; e < e1; e++)
            a += ww[e] * xb[src[e]];
        ax[dir] = a;
    }
    uint2 st;
    st.x = packh(xv, ax[0]);
    st.y = packh(ax[1], 0.f);
    *(uint2*)&g_xc[((size_t)t*M_PAD + r)*4] = st;
}

// ---------------- aggregation: 4 nodes/block, fp16x4 (uint2) gathers ----------
__global__ void __launch_bounds__(256) agg_kernel(int t, int full) {
    const __half* __restrict__ hb = full ? g_hb : g_rhb;
    int tid = threadIdx.x;
    int nl = tid >> 6, b = (tid >> 4) & 3, cp = tid & 15;
    int c  = cp * 4;
    int n  = blockIdx.x*4 + nl;
    int row = n*BATCH + b;
    size_t ub = (size_t)row * KDIM;

    // direct channels: aligned 8B copy from fp16 mirror
    *(uint2*)&g_U[ub + c] = *(const uint2*)&hb[row*HID + c];
    // x channels from precomputed table (full pass only; persist through partial pass)
    if (full && cp == 0)
        *(uint2*)&g_U[ub + 192] = *(const uint2*)&g_xc[((size_t)t*M_PAD + row)*4];

    for (int dir = 0; dir < 2; dir++) {
        const int*   off = dir == 0 ? g_offF : g_offB;
        const int*   src = dir == 0 ? g_srcF : g_srcB;
        const float* ww  = dir == 0 ? g_wF   : g_wB;
        int e0 = off[n], e1 = off[n + 1];
        float a0 = 0.f, a1 = 0.f, a2 = 0.f, a3 = 0.f;
        int e = e0;
        for (; e + 4 <= e1; e += 4) {
            int s0 = src[e], s1 = src[e+1], s2 = src[e+2], s3 = src[e+3];
            float w0 = ww[e], w1 = ww[e+1], w2 = ww[e+2], w3 = ww[e+3];
            uint2 u0 = *(const uint2*)&hb[(s0*BATCH+b)*HID + c];
            uint2 u1 = *(const uint2*)&hb[(s1*BATCH+b)*HID + c];
            uint2 u2 = *(const uint2*)&hb[(s2*BATCH+b)*HID + c];
            uint2 u3 = *(const uint2*)&hb[(s3*BATCH+b)*HID + c];
            __half2 p00 = *(__half2*)&u0.x, p01 = *(__half2*)&u0.y;
            __half2 p10 = *(__half2*)&u1.x, p11 = *(__half2*)&u1.y;
            __half2 p20 = *(__half2*)&u2.x, p21 = *(__half2*)&u2.y;
            __half2 p30 = *(__half2*)&u3.x, p31 = *(__half2*)&u3.y;
            a0 += w0*__low2float(p00)  + w1*__low2float(p10)  + w2*__low2float(p20)  + w3*__low2float(p30);
            a1 += w0*__high2float(p00) + w1*__high2float(p10) + w2*__high2float(p20) + w3*__high2float(p30);
            a2 += w0*__low2float(p01)  + w1*__low2float(p11)  + w2*__low2float(p21)  + w3*__low2float(p31);
            a3 += w0*__high2float(p01) + w1*__high2float(p11) + w2*__high2float(p21) + w3*__high2float(p31);
        }
        for (; e < e1; e++) {
            int s = src[e]; float w = ww[e];
            uint2 u = *(const uint2*)&hb[(s*BATCH+b)*HID + c];
            __half2 p0 = *(__half2*)&u.x, p1 = *(__half2*)&u.y;
            a0 += w*__low2float(p0);
            a1 += w*__high2float(p0);
            a2 += w*__low2float(p1);
            a3 += w*__high2float(p1);
        }
        int chbase = dir == 0 ? 64 : 128;
        uint2 st;
        st.x = packh(a0, a1);
        st.y = packh(a2, a3);
        *(uint2*)&g_U[ub + chbase + c] = st;
    }
}

// ---------------- HMMA GEMM (fp16 A, fp16 hi/lo B), 1m x 8n, B prefetch pipeline ----
__device__ __forceinline__ void mma16816(float* d, const u32* a, const u32* b) {
    asm volatile("mma.sync.aligned.m16n8k16.row.col.f32.f16.f16.f32 "
        "{%0,%1,%2,%3}, {%4,%5,%6,%7}, {%8,%9}, {%0,%1,%2,%3};"
        : "+f"(d[0]), "+f"(d[1]), "+f"(d[2]), "+f"(d[3])
        : "r"(a[0]), "r"(a[1]), "r"(a[2]), "r"(a[3]), "r"(b[0]), "r"(b[1]));
}
__device__ __forceinline__ void ldmx4(u32* r, u32 addr) {
    asm volatile("ldmatrix.sync.aligned.m8n8.x4.shared.b16 {%0,%1,%2,%3}, [%4];"
        : "=r"(r[0]), "=r"(r[1]), "=r"(r[2]), "=r"(r[3]) : "r"(addr));
}
__device__ __forceinline__ float sigf(float v) { return 1.f / (1.f + __expf(-v)); }

template<int NOUT>
__global__ void __launch_bounds__(256) gemm_kernel() {
    constexpr int NATOT = NOUT / 8;
    constexpr int NA    = NOUT / 64;          // natoms per warp (2 for 128, 1 for 64)
    constexpr int WCOL  = NOUT / 8;           // cols per warp

    extern __shared__ __half sA[];            // [64][SPITCH]
    int tid = threadIdx.x;
    int rowBase = blockIdx.x * 64;

    // stage A: 64 rows x 208 cols fp16 = 1664 uint4, coalesced
#pragma unroll
    for (int q = 0; q < 7; q++) {
        int idx = tid + q*256;
        if (idx < 1664) {
            int r = idx / 26, c8 = idx % 26;
            uint4 v = *(const uint4*)(g_U + (size_t)(rowBase + r)*KDIM + c8*8);
            *(uint4*)(sA + r*SPITCH + c8*8) = v;
        }
    }
    __syncthreads();

    int wid = tid >> 5, lane = tid & 31;
    const uint2* __restrict__ Bf = (NOUT == 128) ? g_BfZr : g_BfC;

    u32 aBase = smem_u32(sA);
    int rloc = lane & 15;
    u32 csel = (u32)(lane >> 4) * 16;

    float acc[4][NA][4];
#pragma unroll
    for (int ma = 0; ma < 4; ma++)
#pragma unroll
        for (int j = 0; j < NA; j++)
#pragma unroll
            for (int q = 0; q < 4; q++) acc[ma][j][q] = 0.f;

    // prologue: B fragments for ks=0
    uint2 bh[NA], bl[NA];
#pragma unroll
    for (int j = 0; j < NA; j++) {
        int na = wid*NA + j;
        bh[j] = Bf[(0*NATOT + na)*32 + lane];
        bl[j] = Bf[(1*NATOT + na)*32 + lane];
    }

#pragma unroll 2
    for (int ks = 0; ks < NKS; ks++) {
        u32 kb = (u32)ks * 32;
        u32 a[4][4];
#pragma unroll
        for (int ma = 0; ma < 4; ma++) {
            u32 off = (u32)(rloc + ma*16) * (SPITCH*2) + kb + csel;
            ldmx4(a[ma], aBase + off);
        }
        // prefetch next ks B fragments (overlaps with MMAs below)
        uint2 nbh[NA], nbl[NA];
        if (ks + 1 < NKS) {
#pragma unroll
            for (int j = 0; j < NA; j++) {
                int na = wid*NA + j;
                nbh[j] = Bf[(((ks+1)*2 + 0)*NATOT + na)*32 + lane];
                nbl[j] = Bf[(((ks+1)*2 + 1)*NATOT + na)*32 + lane];
            }
        }
#pragma unroll
        for (int ma = 0; ma < 4; ma++)
#pragma unroll
            for (int j = 0; j < NA; j++) {
                mma16816(acc[ma][j], a[ma], (const u32*)&bh[j]);
                mma16816(acc[ma][j], a[ma], (const u32*)&bl[j]);
            }
        if (ks + 1 < NKS) {
#pragma unroll
            for (int j = 0; j < NA; j++) { bh[j] = nbh[j]; bl[j] = nbl[j]; }
        }
    }

    // epilogue (maintains fp16 mirrors; rh exists ONLY as fp16)
    int rbase = rowBase + (lane >> 2);
#pragma unroll
    for (int ma = 0; ma < 4; ma++) {
#pragma unroll
        for (int j = 0; j < NA; j++) {
            int col = wid*WCOL + j*8 + (lane & 3)*2;
#pragma unroll
            for (int half = 0; half < 2; half++) {
                int row = rbase + ma*16 + half*8;
                float d0 = acc[ma][j][half*2], d1 = acc[ma][j][half*2 + 1];
                if (NOUT == 128) {
                    if (col < 64) {
                        float2 zv = make_float2(sigf(d0 + g_bzr[col]), sigf(d1 + g_bzr[col+1]));
                        *(float2*)&g_z[row*HID + col] = zv;
                    } else {
                        int jr = col - 64;
                        float2 hv = *(const float2*)&g_h[row*HID + jr];
                        float rv0 = sigf(d0 + g_bzr[col]) * hv.x;
                        float rv1 = sigf(d1 + g_bzr[col+1]) * hv.y;
                        *(__half2*)&g_rhb[row*HID + jr] = __floats2half2_rn(rv0, rv1);
                    }
                } else {
                    float c0 = tanhf(d0 + g_bh[col]);
                    float c1 = tanhf(d1 + g_bh[col+1]);
                    float2 zv = *(const float2*)&g_z[row*HID + col];
                    float2 hv = *(const float2*)&g_h[row*HID + col];
                    float2 nh = make_float2(zv.x*hv.x + (1.f - zv.x)*c0,
                                            zv.y*hv.y + (1.f - zv.y)*c1);
                    *(float2*)&g_h[row*HID + col] = nh;
                    *(__half2*)&g_hb[row*HID + col] = __floats2half2_rn(nh.x, nh.y);
                }
            }
        }
    }
}

// ---------------- readout (node 0 only) ----------------
__global__ void readout_kernel(const float* __restrict__ W1, const float* __restrict__ b1,
                               const float* __restrict__ W2, const float* __restrict__ b2,
                               float* __restrict__ out) {
    int tid = threadIdx.x;
    int b = tid >> 6, j = tid & 63;
    float acc = b1[j];
#pragma unroll
    for (int c = 0; c < HID; c++)
        acc += g_h[b*HID + c] * W1[c*HID + j];
    float v = fmaxf(acc, 0.f) * W2[j];
#pragma unroll
    for (int o = 16; o > 0; o >>= 1) v += __shfl_down_sync(0xffffffff, v, o);
    __shared__ float part[8];
    if ((tid & 31) == 0) part[tid >> 5] = v;
    __syncthreads();
    if (j == 0) out[b] = part[b*2] + part[b*2 + 1] + b2[0];
}

// ---------------- launch ----------------
extern "C" void kernel_launch(void* const* d_in, const int* in_sizes, int n_in,
                              void* d_out, int out_size) {
    const float* x_dis = (const float*)d_in[0];
    const int*   ei    = (const int*)  d_in[1];
    const float* ew    = (const float*)d_in[2];
    const float* W_z   = (const float*)d_in[3];
    const float* b_z   = (const float*)d_in[4];
    const float* W_r   = (const float*)d_in[5];
    const float* b_r   = (const float*)d_in[6];
    const float* W_h   = (const float*)d_in[7];
    const float* b_h   = (const float*)d_in[8];
    const float* W_ro1 = (const float*)d_in[9];
    const float* b_ro1 = (const float*)d_in[10];
    const float* W_ro2 = (const float*)d_in[11];
    const float* b_ro2 = (const float*)d_in[12];
    float* out = (float*)d_out;

    const int PREP_SMEM = 4 * 10240 * 4;                 // 160 KB
    const int GEMM_SMEM = 64 * SPITCH * 2;               // 27648 B
    cudaFuncSetAttribute(prep_scan, cudaFuncAttributeMaxDynamicSharedMemorySize, PREP_SMEM);
    cudaFuncSetAttribute(gemm_kernel<128>, cudaFuncAttributeMaxDynamicSharedMemorySize, GEMM_SMEM);
    cudaFuncSetAttribute(gemm_kernel<64>,  cudaFuncAttributeMaxDynamicSharedMemorySize, GEMM_SMEM);

    prep_scan<<<1, 1024, PREP_SMEM>>>(ei, ew);
    fill_misc<<<FILL_BLKS + ZEROH_BLKS + BFRAG_BLKS, 256>>>(ei, ew, W_z, b_z, W_r, b_r, W_h, b_h);
    xagg_kernel<<<(T_STEPS*M_ROWS + 255)/256, 256>>>(x_dis);

    for (int t = 0; t < T_STEPS; t++) {
        agg_kernel<<<N_NODES/4, 256>>>(t, 1);
        gemm_kernel<128><<<M_PAD/64, 256, GEMM_SMEM>>>();
        agg_kernel<<<N_NODES/4, 256>>>(t, 0);
        gemm_kernel<64><<<M_PAD/64, 256, GEMM_SMEM>>>();
    }
    readout_kernel<<<1, 256>>>(W_ro1, b_ro1, W_ro2, b_ro2, out);
}

// round 15
// speedup vs baseline: 1.0856x; 1.0856x over previous
#include <cuda_runtime.h>
#include <cuda_fp16.h>
#include <stdint.h>
#include <math.h>

#define N_NODES 10000
#define N_EDGES 160000
#define BATCH 4
#define T_STEPS 16
#define HID 64
#define M_ROWS 40000
#define M_PAD  40064             // 626 * 64
#define KDIM 208                 // 13 * 16
#define NKS 13
#define SPITCH 216               // smem A pitch in halves (432B: conflict-free ldmatrix)

typedef uint32_t u32;

// U channel layout (K axis, permuted for aligned agg stores):
//   [0..63] = h|rh   [64..127] = aggF(h|rh)   [128..191] = aggB(h|rh)
//   [192]=x [193]=aggF_x [194]=aggB_x [195..207]=0
// Permutation folded into the B fragment tables at build time.

// ---------------- device scratch ----------------
__device__ float g_h [M_PAD*HID];
__device__ float g_z [M_PAD*HID];
__device__ __align__(16) __half g_hb [M_PAD*HID];   // fp16 mirror of h
__device__ __align__(16) __half g_rhb[M_PAD*HID];   // fp16 rh (only representation)
__device__ __align__(16) __half g_U  [(size_t)M_PAD*KDIM];   // fp16 activations (GEMM A)
__device__ __align__(8)  __half g_xc [(size_t)T_STEPS*M_PAD*4]; // {x, aggFx, aggBx, 0}
__device__ float g_deg_out[N_NODES], g_deg_in[N_NODES];
__device__ int   g_cntF[N_NODES], g_cntB[N_NODES];
__device__ int   g_offF[N_NODES+1], g_offB[N_NODES+1];
__device__ __align__(8) int2 g_eF[N_EDGES];   // {src, w as float bits}
__device__ __align__(8) int2 g_eB[N_EDGES];
// Prepacked B fragment tables (fp16 hi/lo): [ks][split][natom][lane] -> uint2
__device__ uint2 g_BfZr[NKS*2*16*32];
__device__ uint2 g_BfC [NKS*2*8*32];
__device__ float g_bzr[128], g_bh[64];

__device__ __forceinline__ u32 smem_u32(const void* p) {
    u32 a;
    asm("{ .reg .u64 t; cvta.to.shared.u64 t, %1; cvt.u32.u64 %0, t; }" : "=r"(a) : "l"(p));
    return a;
}

// ---------------- prep 1: single-block histogram + degree + scan ----------------
__global__ void prep_scan(const int* __restrict__ ei, const float* __restrict__ ew) {
    extern __shared__ int sm[];
    int*   cF = sm;
    int*   cB = sm + 10240;
    float* dF = (float*)(sm + 20480);
    float* dB = (float*)(sm + 30720);
    __shared__ int sb[1024];
    int t = threadIdx.x;

    for (int i = t; i < 10240; i += 1024) { cF[i]=0; cB[i]=0; dF[i]=0.f; dB[i]=0.f; }
    __syncthreads();

    for (int e = t; e < N_EDGES; e += 1024) {
        int r = ei[e], c = ei[N_EDGES + e];
        float w = ew[e];
        atomicAdd(&cF[r], 1);
        atomicAdd(&cB[c], 1);
        atomicAdd(&dF[r], w);
        atomicAdd(&dB[c], w);
    }
    __syncthreads();

    for (int i = t; i < N_NODES; i += 1024) {
        g_deg_out[i] = dF[i];
        g_deg_in [i] = dB[i];
        g_cntF[i] = 0;
        g_cntB[i] = 0;
    }

    for (int pass = 0; pass < 2; pass++) {
        const int* cnt = pass == 0 ? cF : cB;
        int*       off = pass == 0 ? g_offF : g_offB;
        int carry = 0;
        for (int base = 0; base < N_NODES; base += 1024) {
            int v = (base + t < N_NODES) ? cnt[base + t] : 0;
            sb[t] = v; __syncthreads();
            for (int o = 1; o < 1024; o <<= 1) {
                int y = (t >= o) ? sb[t - o] : 0;
                __syncthreads();
                sb[t] += y;
                __syncthreads();
            }
            if (base + t < N_NODES) off[base + t] = carry + sb[t] - v;
            carry += sb[1023];
            __syncthreads();
        }
        if (t == 0) off[N_NODES] = carry;
        __syncthreads();
    }
}

// ---------------- prep 2: edge fill + zero h + B fragment build ----------------
#define FILL_BLKS 625
#define ZEROH_BLKS 10016          // M_PAD*HID/256
#define ZRE (NKS*2*16*32)         // 13312
#define CE  (NKS*2*8*32)          // 6656
#define BFRAG_BLKS 78

// wval over the ORIGINAL channel indexing
__device__ __forceinline__ float wval(const float* W, int c, int j) {
    if (c >= 195) return 0.f;
    if (c < 65)  return W[(0*65 + c)*64 + j] + W[(2*65 + c)*64 + j];
    if (c < 130) return W[(1*65 + (c-65))*64 + j];
    return W[(3*65 + (c-130))*64 + j];
}
// map NEW (permuted) channel -> ORIGINAL channel
__device__ __forceinline__ int newc(int c) {
    if (c < 64)  return c + 1;
    if (c < 128) return c + 2;
    if (c < 192) return c + 3;
    if (c == 192) return 0;
    if (c == 193) return 65;
    if (c == 194) return 130;
    return 999;
}
__device__ __forceinline__ u32 packh(float a, float b) {
    __half2 t = __floats2half2_rn(a, b);
    return *(u32*)&t;
}
__global__ void fill_misc(const int* __restrict__ ei, const float* __restrict__ ew,
                          const float* __restrict__ Wz, const float* __restrict__ bz,
                          const float* __restrict__ Wr, const float* __restrict__ br,
                          const float* __restrict__ Wh, const float* __restrict__ bh) {
    int blk = blockIdx.x, tid = threadIdx.x;
    if (blk < FILL_BLKS) {
        int e = blk*256 + tid;
        if (e >= N_EDGES) return;
        int r = ei[e], c = ei[N_EDGES + e];
        float w = ew[e];
        float dof = g_deg_out[r];
        float cf = (dof > 0.f) ? w / dof : 0.f;
        int p = g_offF[r] + atomicAdd(&g_cntF[r], 1);
        g_eF[p] = make_int2(c, __float_as_int(cf));
        float din = g_deg_in[c];
        float cb = (din > 0.f) ? w / din : 0.f;
        int q = g_offB[c] + atomicAdd(&g_cntB[c], 1);
        g_eB[q] = make_int2(r, __float_as_int(cb));
    } else if (blk < FILL_BLKS + ZEROH_BLKS) {
        int i = (blk - FILL_BLKS)*256 + tid;
        if (i < M_PAD*HID) { g_h[i] = 0.f; g_hb[i] = __float2half(0.f); }
    } else {
        int idx = (blk - FILL_BLKS - ZEROH_BLKS)*256 + tid;
        if (idx < 128) g_bzr[idx] = (idx < 64) ? bz[idx] : br[idx - 64];
        if (idx < 64)  g_bh[idx] = bh[idx];
        if (idx < ZRE + CE) {
            int natot = (idx < ZRE) ? 16 : 8;
            int e = (idx < ZRE) ? idx : idx - ZRE;
            int lane = e & 31;
            int na   = (e >> 5) % natot;
            int split = (e / (32*natot)) & 1;
            int ks    = e / (64*natot);
            int k0 = ks*16 + (lane & 3)*2;
            int n  = na*8 + (lane >> 2);
            float v[4];
            if (idx < ZRE) {
                const float* W = (n < 64) ? Wz : Wr;
                int j = n & 63;
                v[0] = wval(W, newc(k0),   j); v[1] = wval(W, newc(k0+1), j);
                v[2] = wval(W, newc(k0+8), j); v[3] = wval(W, newc(k0+9), j);
            } else {
                v[0] = wval(Wh, newc(k0),   n); v[1] = wval(Wh, newc(k0+1), n);
                v[2] = wval(Wh, newc(k0+8), n); v[3] = wval(Wh, newc(k0+9), n);
            }
            float p[4];
            for (int i2 = 0; i2 < 4; i2++) {
                float hi = __half2float(__float2half(v[i2]));
                p[i2] = split ? (v[i2] - hi) : hi;
            }
            uint2 frag = make_uint2(packh(p[0], p[1]), packh(p[2], p[3]));
            if (idx < ZRE) g_BfZr[e] = frag; else g_BfC[e] = frag;
        }
    }
}

// ---------------- prep 3: x-channel aggregation for ALL steps (h-independent) ----
__global__ void xagg_kernel(const float* __restrict__ x_dis) {
    int idx = blockIdx.x*blockDim.x + threadIdx.x;     // over 16 * 40000
    if (idx >= T_STEPS*M_ROWS) return;
    int t = idx / M_ROWS, r = idx % M_ROWS;
    int n = r >> 2, b = r & 3;
    const float* __restrict__ xb = x_dis + (size_t)(b*T_STEPS + t)*N_NODES;
    float xv = xb[n];
    float ax[2];
    for (int dir = 0; dir < 2; dir++) {
        const int*  off = dir == 0 ? g_offF : g_offB;
        const int2* eds = dir == 0 ? g_eF   : g_eB;
        float a = 0.f;
        int e1 = off[n + 1];
        for (int e = off[n]; e < e1; e++) {
            int2 ed = eds[e];
            a += __int_as_float(ed.y) * xb[ed.x];
        }
        ax[dir] = a;
    }
    uint2 st;
    st.x = packh(xv, ax[0]);
    st.y = packh(ax[1], 0.f);
    *(uint2*)&g_xc[((size_t)t*M_PAD + r)*4] = st;
}

// ---------------- aggregation: 8 nodes/block, 8 ch/thread, uint4 gathers ----------
struct Acc8 { float a0,a1,a2,a3,a4,a5,a6,a7; };
__device__ __forceinline__ void acc8(Acc8& A, uint4 u, float w) {
    __half2 q0 = *(__half2*)&u.x, q1 = *(__half2*)&u.y;
    __half2 q2 = *(__half2*)&u.z, q3 = *(__half2*)&u.w;
    A.a0 += w*__low2float(q0); A.a1 += w*__high2float(q0);
    A.a2 += w*__low2float(q1); A.a3 += w*__high2float(q1);
    A.a4 += w*__low2float(q2); A.a5 += w*__high2float(q2);
    A.a6 += w*__low2float(q3); A.a7 += w*__high2float(q3);
}
__global__ void __launch_bounds__(256) agg_kernel(int t, int full) {
    const __half* __restrict__ hb = full ? g_hb : g_rhb;
    int tid = threadIdx.x;
    int nl = tid >> 5, b = (tid >> 3) & 3, cp = tid & 7;
    int c  = cp * 8;
    int n  = blockIdx.x*8 + nl;
    int row = n*BATCH + b;
    size_t ub = (size_t)row * KDIM;

    // direct channels: aligned 16B copy from fp16 mirror
    *(uint4*)&g_U[ub + c] = *(const uint4*)&hb[row*HID + c];
    // x channels from precomputed table (full pass only; persist through partial pass)
    if (full && cp == 0)
        *(uint2*)&g_U[ub + 192] = *(const uint2*)&g_xc[((size_t)t*M_PAD + row)*4];

    for (int dir = 0; dir < 2; dir++) {
        const int*  off = dir == 0 ? g_offF : g_offB;
        const int2* __restrict__ eds = dir == 0 ? g_eF : g_eB;
        int e0 = off[n], e1 = off[n + 1];
        Acc8 A = {0.f,0.f,0.f,0.f,0.f,0.f,0.f,0.f};
        int e = e0;
        for (; e + 4 <= e1; e += 4) {
            int2 d0 = eds[e], d1 = eds[e+1], d2 = eds[e+2], d3 = eds[e+3];
            uint4 u0 = *(const uint4*)&hb[(d0.x*BATCH+b)*HID + c];
            uint4 u1 = *(const uint4*)&hb[(d1.x*BATCH+b)*HID + c];
            uint4 u2 = *(const uint4*)&hb[(d2.x*BATCH+b)*HID + c];
            uint4 u3 = *(const uint4*)&hb[(d3.x*BATCH+b)*HID + c];
            acc8(A, u0, __int_as_float(d0.y));
            acc8(A, u1, __int_as_float(d1.y));
            acc8(A, u2, __int_as_float(d2.y));
            acc8(A, u3, __int_as_float(d3.y));
        }
        for (; e < e1; e++) {
            int2 d = eds[e];
            uint4 u = *(const uint4*)&hb[(d.x*BATCH+b)*HID + c];
            acc8(A, u, __int_as_float(d.y));
        }
        int chbase = dir == 0 ? 64 : 128;
        uint4 st;
        st.x = packh(A.a0, A.a1); st.y = packh(A.a2, A.a3);
        st.z = packh(A.a4, A.a5); st.w = packh(A.a6, A.a7);
        *(uint4*)&g_U[ub + chbase + c] = st;
    }
}

// ---------------- HMMA GEMM (fp16 A, fp16 hi/lo B), 1m x 8n warp layout ----------
__device__ __forceinline__ void mma16816(float* d, const u32* a, const u32* b) {
    asm volatile("mma.sync.aligned.m16n8k16.row.col.f32.f16.f16.f32 "
        "{%0,%1,%2,%3}, {%4,%5,%6,%7}, {%8,%9}, {%0,%1,%2,%3};"
        : "+f"(d[0]), "+f"(d[1]), "+f"(d[2]), "+f"(d[3])
        : "r"(a[0]), "r"(a[1]), "r"(a[2]), "r"(a[3]), "r"(b[0]), "r"(b[1]));
}
__device__ __forceinline__ void ldmx4(u32* r, u32 addr) {
    asm volatile("ldmatrix.sync.aligned.m8n8.x4.shared.b16 {%0,%1,%2,%3}, [%4];"
        : "=r"(r[0]), "=r"(r[1]), "=r"(r[2]), "=r"(r[3]) : "r"(addr));
}
__device__ __forceinline__ float sigf(float v) { return 1.f / (1.f + __expf(-v)); }

// BM=64, 256 threads = 8 warps, all warps span 64 rows; warp wid owns its col slice.
template<int NOUT>
__global__ void __launch_bounds__(256) gemm_kernel() {
    constexpr int NATOT = NOUT / 8;
    constexpr int NA    = NOUT / 64;
    constexpr int WCOL  = NOUT / 8;

    extern __shared__ __half sA[];            // [64][SPITCH]
    int tid = threadIdx.x;
    int rowBase = blockIdx.x * 64;

#pragma unroll
    for (int q = 0; q < 7; q++) {
        int idx = tid + q*256;
        if (idx < 1664) {
            int r = idx / 26, c8 = idx % 26;
            uint4 v = *(const uint4*)(g_U + (size_t)(rowBase + r)*KDIM + c8*8);
            *(uint4*)(sA + r*SPITCH + c8*8) = v;
        }
    }
    __syncthreads();

    int wid = tid >> 5, lane = tid & 31;
    const uint2* __restrict__ Bf = (NOUT == 128) ? g_BfZr : g_BfC;

    u32 aBase = smem_u32(sA);
    int rloc = lane & 15;
    u32 csel = (u32)(lane >> 4) * 16;

    float acc[4][NA][4];
#pragma unroll
    for (int ma = 0; ma < 4; ma++)
#pragma unroll
        for (int j = 0; j < NA; j++)
#pragma unroll
            for (int q = 0; q < 4; q++) acc[ma][j][q] = 0.f;

#pragma unroll 1
    for (int ks = 0; ks < NKS; ks++) {
        u32 kb = (u32)ks * 32;
        u32 a[4][4];
#pragma unroll
        for (int ma = 0; ma < 4; ma++) {
            u32 off = (u32)(rloc + ma*16) * (SPITCH*2) + kb + csel;
            ldmx4(a[ma], aBase + off);
        }
        uint2 bh[NA], bl[NA];
#pragma unroll
        for (int j = 0; j < NA; j++) {
            int na = wid*NA + j;
            bh[j] = Bf[((ks*2 + 0)*NATOT + na)*32 + lane];
            bl[j] = Bf[((ks*2 + 1)*NATOT + na)*32 + lane];
        }
#pragma unroll
        for (int ma = 0; ma < 4; ma++)
#pragma unroll
            for (int j = 0; j < NA; j++) {
                mma16816(acc[ma][j], a[ma], (const u32*)&bh[j]);
                mma16816(acc[ma][j], a[ma], (const u32*)&bl[j]);
            }
    }

    // epilogue (maintains fp16 mirrors; rh exists ONLY as fp16)
    int rbase = rowBase + (lane >> 2);
#pragma unroll
    for (int ma = 0; ma < 4; ma++) {
#pragma unroll
        for (int j = 0; j < NA; j++) {
            int col = wid*WCOL + j*8 + (lane & 3)*2;
#pragma unroll
            for (int half = 0; half < 2; half++) {
                int row = rbase + ma*16 + half*8;
                float d0 = acc[ma][j][half*2], d1 = acc[ma][j][half*2 + 1];
                if (NOUT == 128) {
                    if (col < 64) {
                        float2 zv = make_float2(sigf(d0 + g_bzr[col]), sigf(d1 + g_bzr[col+1]));
                        *(float2*)&g_z[row*HID + col] = zv;
                    } else {
                        int jr = col - 64;
                        float2 hv = *(const float2*)&g_h[row*HID + jr];
                        float rv0 = sigf(d0 + g_bzr[col]) * hv.x;
                        float rv1 = sigf(d1 + g_bzr[col+1]) * hv.y;
                        *(__half2*)&g_rhb[row*HID + jr] = __floats2half2_rn(rv0, rv1);
                    }
                } else {
                    float c0 = tanhf(d0 + g_bh[col]);
                    float c1 = tanhf(d1 + g_bh[col+1]);
                    float2 zv = *(const float2*)&g_z[row*HID + col];
                    float2 hv = *(const float2*)&g_h[row*HID + col];
                    float2 nh = make_float2(zv.x*hv.x + (1.f - zv.x)*c0,
                                            zv.y*hv.y + (1.f - zv.y)*c1);
                    *(float2*)&g_h[row*HID + col] = nh;
                    *(__half2*)&g_hb[row*HID + col] = __floats2half2_rn(nh.x, nh.y);
                }
            }
        }
    }
}

// ---------------- readout (node 0 only) ----------------
__global__ void readout_kernel(const float* __restrict__ W1, const float* __restrict__ b1,
                               const float* __restrict__ W2, const float* __restrict__ b2,
                               float* __restrict__ out) {
    int tid = threadIdx.x;
    int b = tid >> 6, j = tid & 63;
    float acc = b1[j];
#pragma unroll
    for (int c = 0; c < HID; c++)
        acc += g_h[b*HID + c] * W1[c*HID + j];
    float v = fmaxf(acc, 0.f) * W2[j];
#pragma unroll
    for (int o = 16; o > 0; o >>= 1) v += __shfl_down_sync(0xffffffff, v, o);
    __shared__ float part[8];
    if ((tid & 31) == 0) part[tid >> 5] = v;
    __syncthreads();
    if (j == 0) out[b] = part[b*2] + part[b*2 + 1] + b2[0];
}

// ---------------- launch ----------------
extern "C" void kernel_launch(void* const* d_in, const int* in_sizes, int n_in,
                              void* d_out, int out_size) {
    const float* x_dis = (const float*)d_in[0];
    const int*   ei    = (const int*)  d_in[1];
    const float* ew    = (const float*)d_in[2];
    const float* W_z   = (const float*)d_in[3];
    const float* b_z   = (const float*)d_in[4];
    const float* W_r   = (const float*)d_in[5];
    const float* b_r   = (const float*)d_in[6];
    const float* W_h   = (const float*)d_in[7];
    const float* b_h   = (const float*)d_in[8];
    const float* W_ro1 = (const float*)d_in[9];
    const float* b_ro1 = (const float*)d_in[10];
    const float* W_ro2 = (const float*)d_in[11];
    const float* b_ro2 = (const float*)d_in[12];
    float* out = (float*)d_out;

    const int PREP_SMEM = 4 * 10240 * 4;                 // 160 KB
    const int GEMM_SMEM = 64 * SPITCH * 2;               // 27648 B
    cudaFuncSetAttribute(prep_scan, cudaFuncAttributeMaxDynamicSharedMemorySize, PREP_SMEM);
    cudaFuncSetAttribute(gemm_kernel<128>, cudaFuncAttributeMaxDynamicSharedMemorySize, GEMM_SMEM);
    cudaFuncSetAttribute(gemm_kernel<64>,  cudaFuncAttributeMaxDynamicSharedMemorySize, GEMM_SMEM);

    prep_scan<<<1, 1024, PREP_SMEM>>>(ei, ew);
    fill_misc<<<FILL_BLKS + ZEROH_BLKS + BFRAG_BLKS, 256>>>(ei, ew, W_z, b_z, W_r, b_r, W_h, b_h);
    xagg_kernel<<<(T_STEPS*M_ROWS + 255)/256, 256>>>(x_dis);

    for (int t = 0; t < T_STEPS; t++) {
        agg_kernel<<<N_NODES/8, 256>>>(t, 1);
        gemm_kernel<128><<<M_PAD/64, 256, GEMM_SMEM>>>();
        agg_kernel<<<N_NODES/8, 256>>>(t, 0);
        gemm_kernel<64><<<M_PAD/64, 256, GEMM_SMEM>>>();
    }
    readout_kernel<<<1, 256>>>(W_ro1, b_ro1, W_ro2, b_ro2, out);
}

// round 17
// speedup vs baseline: 1.1304x; 1.0413x over previous
#include <cuda_runtime.h>
#include <cuda_fp16.h>
#include <stdint.h>
#include <math.h>

#define N_NODES 10000
#define N_EDGES 160000
#define BATCH 4
#define T_STEPS 16
#define HID 64
#define M_ROWS 40000
#define M_PAD  40064             // 626 * 64
#define KDIM 208                 // 13 * 16
#define NKS 13
#define SPITCH 216               // smem A pitch in halves (432B: conflict-free ldmatrix)

typedef uint32_t u32;

// U channel layout (K axis, permuted for aligned agg stores):
//   [0..63] = h|rh   [64..127] = aggF(h|rh)   [128..191] = aggB(h|rh)
//   [192]=x [193]=aggF_x [194]=aggB_x [195..207]=0
// Permutation folded into the B fragment tables at build time.

// ---------------- device scratch ----------------
__device__ float g_h [M_PAD*HID];                   // fp32 recurrence state
__device__ __align__(16) __half g_zb [M_PAD*HID];   // fp16 z gate
__device__ __align__(16) __half g_hb [M_PAD*HID];   // fp16 mirror of h
__device__ __align__(16) __half g_rhb[M_PAD*HID];   // fp16 rh (only representation)
__device__ __align__(16) __half g_U  [(size_t)M_PAD*KDIM];   // fp16 activations (GEMM A)
__device__ __align__(8)  __half g_xc [(size_t)T_STEPS*M_PAD*4]; // {x, aggFx, aggBx, 0}
__device__ int   g_cntF[N_NODES], g_cntB[N_NODES];
__device__ int   g_offF[N_NODES+1], g_offB[N_NODES+1];
__device__ __align__(8) int2 g_eF[N_EDGES];   // {src, w bits} (raw w, then coef after sortcoef)
__device__ __align__(8) int2 g_eB[N_EDGES];
__device__ int   g_idF[N_EDGES], g_idB[N_EDGES];   // original edge ids (sort keys)
// Prepacked B fragment tables (fp16 hi/lo): [ks][split][natom][lane] -> uint2
__device__ uint2 g_BfZr[NKS*2*16*32];
__device__ uint2 g_BfC [NKS*2*8*32];
__device__ float g_bzr[128], g_bh[64];

__device__ __forceinline__ u32 smem_u32(const void* p) {
    u32 a;
    asm("{ .reg .u64 t; cvta.to.shared.u64 t, %1; cvt.u32.u64 %0, t; }" : "=r"(a) : "l"(p));
    return a;
}

// ---------------- prep 1: single-block histogram (int counts only) + scan ----------------
__global__ void prep_scan(const int* __restrict__ ei) {
    extern __shared__ int sm[];
    int* cF = sm;
    int* cB = sm + 10240;
    __shared__ int sb[1024];
    int t = threadIdx.x;

    for (int i = t; i < 10240; i += 1024) { cF[i]=0; cB[i]=0; }
    __syncthreads();

    for (int e = t; e < N_EDGES; e += 1024) {
        atomicAdd(&cF[ei[e]], 1);
        atomicAdd(&cB[ei[N_EDGES + e]], 1);
    }
    __syncthreads();

    for (int i = t; i < N_NODES; i += 1024) { g_cntF[i] = 0; g_cntB[i] = 0; }

    for (int pass = 0; pass < 2; pass++) {
        const int* cnt = pass == 0 ? cF : cB;
        int*       off = pass == 0 ? g_offF : g_offB;
        int carry = 0;
        for (int base = 0; base < N_NODES; base += 1024) {
            int v = (base + t < N_NODES) ? cnt[base + t] : 0;
            sb[t] = v; __syncthreads();
            for (int o = 1; o < 1024; o <<= 1) {
                int y = (t >= o) ? sb[t - o] : 0;
                __syncthreads();
                sb[t] += y;
                __syncthreads();
            }
            if (base + t < N_NODES) off[base + t] = carry + sb[t] - v;
            carry += sb[1023];
            __syncthreads();
        }
        if (t == 0) off[N_NODES] = carry;
        __syncthreads();
    }
}

// ---------------- prep 2: edge placement (raw w + id) + zero h + B fragment build ----
#define FILL_BLKS 625
#define ZEROH_BLKS 10016          // M_PAD*HID/256
#define ZRE (NKS*2*16*32)         // 13312
#define CE  (NKS*2*8*32)          // 6656
#define BFRAG_BLKS 78

// wval over the ORIGINAL channel indexing
__device__ __forceinline__ float wval(const float* W, int c, int j) {
    if (c >= 195) return 0.f;
    if (c < 65)  return W[(0*65 + c)*64 + j] + W[(2*65 + c)*64 + j];
    if (c < 130) return W[(1*65 + (c-65))*64 + j];
    return W[(3*65 + (c-130))*64 + j];
}
// map NEW (permuted) channel -> ORIGINAL channel
__device__ __forceinline__ int newc(int c) {
    if (c < 64)  return c + 1;
    if (c < 128) return c + 2;
    if (c < 192) return c + 3;
    if (c == 192) return 0;
    if (c == 193) return 65;
    if (c == 194) return 130;
    return 999;
}
__device__ __forceinline__ u32 packh(float a, float b) {
    __half2 t = __floats2half2_rn(a, b);
    return *(u32*)&t;
}
__global__ void fill_misc(const int* __restrict__ ei, const float* __restrict__ ew,
                          const float* __restrict__ Wz, const float* __restrict__ bz,
                          const float* __restrict__ Wr, const float* __restrict__ br,
                          const float* __restrict__ Wh, const float* __restrict__ bh) {
    int blk = blockIdx.x, tid = threadIdx.x;
    if (blk < FILL_BLKS) {
        int e = blk*256 + tid;
        if (e >= N_EDGES) return;
        int r = ei[e], c = ei[N_EDGES + e];
        int wb = __float_as_int(ew[e]);
        int p = g_offF[r] + atomicAdd(&g_cntF[r], 1);
        g_eF[p] = make_int2(c, wb);
        g_idF[p] = e;
        int q = g_offB[c] + atomicAdd(&g_cntB[c], 1);
        g_eB[q] = make_int2(r, wb);
        g_idB[q] = e;
    } else if (blk < FILL_BLKS + ZEROH_BLKS) {
        int i = (blk - FILL_BLKS)*256 + tid;
        if (i < M_PAD*HID) { g_h[i] = 0.f; g_hb[i] = __float2half(0.f); }
    } else {
        int idx = (blk - FILL_BLKS - ZEROH_BLKS)*256 + tid;
        if (idx < 128) g_bzr[idx] = (idx < 64) ? bz[idx] : br[idx - 64];
        if (idx < 64)  g_bh[idx] = bh[idx];
        if (idx < ZRE + CE) {
            int natot = (idx < ZRE) ? 16 : 8;
            int e = (idx < ZRE) ? idx : idx - ZRE;
            int lane = e & 31;
            int na   = (e >> 5) % natot;
            int split = (e / (32*natot)) & 1;
            int ks    = e / (64*natot);
            int k0 = ks*16 + (lane & 3)*2;
            int n  = na*8 + (lane >> 2);
            float v[4];
            if (idx < ZRE) {
                const float* W = (n < 64) ? Wz : Wr;
                int j = n & 63;
                v[0] = wval(W, newc(k0),   j); v[1] = wval(W, newc(k0+1), j);
                v[2] = wval(W, newc(k0+8), j); v[3] = wval(W, newc(k0+9), j);
            } else {
                v[0] = wval(Wh, newc(k0),   n); v[1] = wval(Wh, newc(k0+1), n);
                v[2] = wval(Wh, newc(k0+8), n); v[3] = wval(Wh, newc(k0+9), n);
            }
            float p[4];
            for (int i2 = 0; i2 < 4; i2++) {
                float hi = __half2float(__float2half(v[i2]));
                p[i2] = split ? (v[i2] - hi) : hi;
            }
            uint2 frag = make_uint2(packh(p[0], p[1]), packh(p[2], p[3]));
            if (idx < ZRE) g_BfZr[e] = frag; else g_BfC[e] = frag;
        }
    }
}

// ---------------- prep 2b: deterministic segment sort + degree + coefficients ----------
// One thread per (node, dir). Insertion-sort segment by original edge id, then
// serial (deterministic-order) degree sum and in-place coef = w/deg.
__global__ void sortcoef_kernel() {
    int idx = blockIdx.x*blockDim.x + threadIdx.x;
    if (idx >= 2*N_NODES) return;
    int dir = idx >= N_NODES;
    int n = dir ? idx - N_NODES : idx;
    const int* off = dir ? g_offB : g_offF;
    int2* eds = dir ? g_eB : g_eF;
    int*  ids = dir ? g_idB : g_idF;
    int e0 = off[n], e1 = off[n + 1];
    // insertion sort by edge id (stable, deterministic)
    for (int i = e0 + 1; i < e1; i++) {
        int2 ev = eds[i];
        int  id = ids[i];
        int j = i - 1;
        while (j >= e0 && ids[j] > id) {
            eds[j+1] = eds[j];
            ids[j+1] = ids[j];
            j--;
        }
        eds[j+1] = ev;
        ids[j+1] = id;
    }
    // deterministic serial degree sum
    float deg = 0.f;
    for (int e = e0; e < e1; e++) deg += __int_as_float(eds[e].y);
    float inv = (deg > 0.f) ? 1.f / deg : 0.f;
    for (int e = e0; e < e1; e++) {
        float w = __int_as_float(eds[e].y);
        eds[e].y = __float_as_int(w * inv);
    }
}

// ---------------- prep 3: x-channel aggregation for ALL steps (h-independent) ----
__global__ void xagg_kernel(const float* __restrict__ x_dis) {
    int idx = blockIdx.x*blockDim.x + threadIdx.x;     // over 16 * 40000
    if (idx >= T_STEPS*M_ROWS) return;
    int t = idx / M_ROWS, r = idx % M_ROWS;
    int n = r >> 2, b = r & 3;
    const float* __restrict__ xb = x_dis + (size_t)(b*T_STEPS + t)*N_NODES;
    float xv = xb[n];
    float ax[2];
    for (int dir = 0; dir < 2; dir++) {
        const int*  off = dir == 0 ? g_offF : g_offB;
        const int2* eds = dir == 0 ? g_eF   : g_eB;
        float a = 0.f;
        int e1 = off[n + 1];
        for (int e = off[n]; e < e1; e++) {
            int2 ed = eds[e];
            a += __int_as_float(ed.y) * xb[ed.x];
        }
        ax[dir] = a;
    }
    uint2 st;
    st.x = packh(xv, ax[0]);
    st.y = packh(ax[1], 0.f);
    *(uint2*)&g_xc[((size_t)t*M_PAD + r)*4] = st;
}

// ---------------- aggregation: 8 nodes/block, 8 ch/thread, uint4 gathers ----------
struct Acc8 { float a0,a1,a2,a3,a4,a5,a6,a7; };
__device__ __forceinline__ void acc8(Acc8& A, uint4 u, float w) {
    __half2 q0 = *(__half2*)&u.x, q1 = *(__half2*)&u.y;
    __half2 q2 = *(__half2*)&u.z, q3 = *(__half2*)&u.w;
    A.a0 += w*__low2float(q0); A.a1 += w*__high2float(q0);
    A.a2 += w*__low2float(q1); A.a3 += w*__high2float(q1);
    A.a4 += w*__low2float(q2); A.a5 += w*__high2float(q2);
    A.a6 += w*__low2float(q3); A.a7 += w*__high2float(q3);
}
__global__ void __launch_bounds__(256) agg_kernel(int t, int full) {
    const __half* __restrict__ hb = full ? g_hb : g_rhb;
    int tid = threadIdx.x;
    int nl = tid >> 5, b = (tid >> 3) & 3, cp = tid & 7;
    int c  = cp * 8;
    int n  = blockIdx.x*8 + nl;
    int row = n*BATCH + b;
    size_t ub = (size_t)row * KDIM;

    // direct channels: aligned 16B copy from fp16 mirror
    *(uint4*)&g_U[ub + c] = *(const uint4*)&hb[row*HID + c];
    // x channels from precomputed table (full pass only; persist through partial pass)
    if (full && cp == 0)
        *(uint2*)&g_U[ub + 192] = *(const uint2*)&g_xc[((size_t)t*M_PAD + row)*4];

    for (int dir = 0; dir < 2; dir++) {
        const int*  off = dir == 0 ? g_offF : g_offB;
        const int2* __restrict__ eds = dir == 0 ? g_eF : g_eB;
        int e0 = off[n], e1 = off[n + 1];
        Acc8 A = {0.f,0.f,0.f,0.f,0.f,0.f,0.f,0.f};
        int e = e0;
        for (; e + 4 <= e1; e += 4) {
            int2 d0 = eds[e], d1 = eds[e+1], d2 = eds[e+2], d3 = eds[e+3];
            uint4 u0 = *(const uint4*)&hb[(d0.x*BATCH+b)*HID + c];
            uint4 u1 = *(const uint4*)&hb[(d1.x*BATCH+b)*HID + c];
            uint4 u2 = *(const uint4*)&hb[(d2.x*BATCH+b)*HID + c];
            uint4 u3 = *(const uint4*)&hb[(d3.x*BATCH+b)*HID + c];
            acc8(A, u0, __int_as_float(d0.y));
            acc8(A, u1, __int_as_float(d1.y));
            acc8(A, u2, __int_as_float(d2.y));
            acc8(A, u3, __int_as_float(d3.y));
        }
        for (; e < e1; e++) {
            int2 d = eds[e];
            uint4 u = *(const uint4*)&hb[(d.x*BATCH+b)*HID + c];
            acc8(A, u, __int_as_float(d.y));
        }
        int chbase = dir == 0 ? 64 : 128;
        uint4 st;
        st.x = packh(A.a0, A.a1); st.y = packh(A.a2, A.a3);
        st.z = packh(A.a4, A.a5); st.w = packh(A.a6, A.a7);
        *(uint4*)&g_U[ub + chbase + c] = st;
    }
}

// ---------------- HMMA GEMM (fp16 A, fp16 hi/lo B), 1m x 8n warp layout ----------
__device__ __forceinline__ void mma16816(float* d, const u32* a, const u32* b) {
    asm volatile("mma.sync.aligned.m16n8k16.row.col.f32.f16.f16.f32 "
        "{%0,%1,%2,%3}, {%4,%5,%6,%7}, {%8,%9}, {%0,%1,%2,%3};"
        : "+f"(d[0]), "+f"(d[1]), "+f"(d[2]), "+f"(d[3])
        : "r"(a[0]), "r"(a[1]), "r"(a[2]), "r"(a[3]), "r"(b[0]), "r"(b[1]));
}
__device__ __forceinline__ void ldmx4(u32* r, u32 addr) {
    asm volatile("ldmatrix.sync.aligned.m8n8.x4.shared.b16 {%0,%1,%2,%3}, [%4];"
        : "=r"(r[0]), "=r"(r[1]), "=r"(r[2]), "=r"(r[3]) : "r"(addr));
}
__device__ __forceinline__ float sigf(float v) { return 1.f / (1.f + __expf(-v)); }

// BM=64, 256 threads = 8 warps, all warps span 64 rows; warp wid owns its col slice.
template<int NOUT>
__global__ void __launch_bounds__(256) gemm_kernel() {
    constexpr int NATOT = NOUT / 8;
    constexpr int NA    = NOUT / 64;
    constexpr int WCOL  = NOUT / 8;

    extern __shared__ __half sA[];            // [64][SPITCH]
    int tid = threadIdx.x;
    int rowBase = blockIdx.x * 64;

#pragma unroll
    for (int q = 0; q < 7; q++) {
        int idx = tid + q*256;
        if (idx < 1664) {
            int r = idx / 26, c8 = idx % 26;
            uint4 v = *(const uint4*)(g_U + (size_t)(rowBase + r)*KDIM + c8*8);
            *(uint4*)(sA + r*SPITCH + c8*8) = v;
        }
    }
    __syncthreads();

    int wid = tid >> 5, lane = tid & 31;
    const uint2* __restrict__ Bf = (NOUT == 128) ? g_BfZr : g_BfC;

    u32 aBase = smem_u32(sA);
    int rloc = lane & 15;
    u32 csel = (u32)(lane >> 4) * 16;

    float acc[4][NA][4];
#pragma unroll
    for (int ma = 0; ma < 4; ma++)
#pragma unroll
        for (int j = 0; j < NA; j++)
#pragma unroll
            for (int q = 0; q < 4; q++) acc[ma][j][q] = 0.f;

#pragma unroll 1
    for (int ks = 0; ks < NKS; ks++) {
        u32 kb = (u32)ks * 32;
        u32 a[4][4];
#pragma unroll
        for (int ma = 0; ma < 4; ma++) {
            u32 off = (u32)(rloc + ma*16) * (SPITCH*2) + kb + csel;
            ldmx4(a[ma], aBase + off);
        }
        uint2 bh[NA], bl[NA];
#pragma unroll
        for (int j = 0; j < NA; j++) {
            int na = wid*NA + j;
            bh[j] = Bf[((ks*2 + 0)*NATOT + na)*32 + lane];
            bl[j] = Bf[((ks*2 + 1)*NATOT + na)*32 + lane];
        }
#pragma unroll
        for (int ma = 0; ma < 4; ma++)
#pragma unroll
            for (int j = 0; j < NA; j++) {
                mma16816(acc[ma][j], a[ma], (const u32*)&bh[j]);
                mma16816(acc[ma][j], a[ma], (const u32*)&bl[j]);
            }
    }

    // epilogue (all gate/state side-traffic in fp16; g_h stays fp32)
    int rbase = rowBase + (lane >> 2);
#pragma unroll
    for (int ma = 0; ma < 4; ma++) {
#pragma unroll
        for (int j = 0; j < NA; j++) {
            int col = wid*WCOL + j*8 + (lane & 3)*2;
#pragma unroll
            for (int half = 0; half < 2; half++) {
                int row = rbase + ma*16 + half*8;
                float d0 = acc[ma][j][half*2], d1 = acc[ma][j][half*2 + 1];
                if (NOUT == 128) {
                    if (col < 64) {
                        *(__half2*)&g_zb[row*HID + col] =
                            __floats2half2_rn(sigf(d0 + g_bzr[col]), sigf(d1 + g_bzr[col+1]));
                    } else {
                        int jr = col - 64;
                        __half2 hv = *(const __half2*)&g_hb[row*HID + jr];
                        float rv0 = sigf(d0 + g_bzr[col]) * __low2float(hv);
                        float rv1 = sigf(d1 + g_bzr[col+1]) * __high2float(hv);
                        *(__half2*)&g_rhb[row*HID + jr] = __floats2half2_rn(rv0, rv1);
                    }
                } else {
                    float c0 = tanhf(d0 + g_bh[col]);
                    float c1 = tanhf(d1 + g_bh[col+1]);
                    __half2 zh = *(const __half2*)&g_zb[row*HID + col];
                    float z0 = __low2float(zh), z1 = __high2float(zh);
                    float2 hv = *(const float2*)&g_h[row*HID + col];
                    float2 nh = make_float2(z0*hv.x + (1.f - z0)*c0,
                                            z1*hv.y + (1.f - z1)*c1);
                    *(float2*)&g_h[row*HID + col] = nh;
                    *(__half2*)&g_hb[row*HID + col] = __floats2half2_rn(nh.x, nh.y);
                }
            }
        }
    }
}

// ---------------- readout (node 0 only) ----------------
__global__ void readout_kernel(const float* __restrict__ W1, const float* __restrict__ b1,
                               const float* __restrict__ W2, const float* __restrict__ b2,
                               float* __restrict__ out) {
    int tid = threadIdx.x;
    int b = tid >> 6, j = tid & 63;
    float acc = b1[j];
#pragma unroll
    for (int c = 0; c < HID; c++)
        acc += g_h[b*HID + c] * W1[c*HID + j];
    float v = fmaxf(acc, 0.f) * W2[j];
#pragma unroll
    for (int o = 16; o > 0; o >>= 1) v += __shfl_down_sync(0xffffffff, v, o);
    __shared__ float part[8];
    if ((tid & 31) == 0) part[tid >> 5] = v;
    __syncthreads();
    if (j == 0) out[b] = part[b*2] + part[b*2 + 1] + b2[0];
}

// ---------------- launch ----------------
extern "C" void kernel_launch(void* const* d_in, const int* in_sizes, int n_in,
                              void* d_out, int out_size) {
    const float* x_dis = (const float*)d_in[0];
    const int*   ei    = (const int*)  d_in[1];
    const float* ew    = (const float*)d_in[2];
    const float* W_z   = (const float*)d_in[3];
    const float* b_z   = (const float*)d_in[4];
    const float* W_r   = (const float*)d_in[5];
    const float* b_r   = (const float*)d_in[6];
    const float* W_h   = (const float*)d_in[7];
    const float* b_h   = (const float*)d_in[8];
    const float* W_ro1 = (const float*)d_in[9];
    const float* b_ro1 = (const float*)d_in[10];
    const float* W_ro2 = (const float*)d_in[11];
    const float* b_ro2 = (const float*)d_in[12];
    float* out = (float*)d_out;

    const int PREP_SMEM = 2 * 10240 * 4;                 // 80 KB
    const int GEMM_SMEM = 64 * SPITCH * 2;               // 27648 B
    cudaFuncSetAttribute(prep_scan, cudaFuncAttributeMaxDynamicSharedMemorySize, PREP_SMEM);
    cudaFuncSetAttribute(gemm_kernel<128>, cudaFuncAttributeMaxDynamicSharedMemorySize, GEMM_SMEM);
    cudaFuncSetAttribute(gemm_kernel<64>,  cudaFuncAttributeMaxDynamicSharedMemorySize, GEMM_SMEM);

    prep_scan<<<1, 1024, PREP_SMEM>>>(ei);
    fill_misc<<<FILL_BLKS + ZEROH_BLKS + BFRAG_BLKS, 256>>>(ei, ew, W_z, b_z, W_r, b_r, W_h, b_h);
    sortcoef_kernel<<<(2*N_NODES + 255)/256, 256>>>();
    xagg_kernel<<<(T_STEPS*M_ROWS + 255)/256, 256>>>(x_dis);

    for (int t = 0; t < T_STEPS; t++) {
        agg_kernel<<<N_NODES/8, 256>>>(t, 1);
        gemm_kernel<128><<<M_PAD/64, 256, GEMM_SMEM>>>();
        agg_kernel<<<N_NODES/8, 256>>>(t, 0);
        gemm_kernel<64><<<M_PAD/64, 256, GEMM_SMEM>>>();
    }
    readout_kernel<<<1, 256>>>(W_ro1, b_ro1, W_ro2, b_ro2, out);
}